// round 10
// baseline (speedup 1.0000x reference)
#include <cuda_runtime.h>
#include <cstdint>

#define NN 50000
#define NE 1600000
#define IND 128
#define HD 64
#define NR 5
#define SA_STRIDE 68
#define NEG_SLOPE 0.01f
#define NCHUNK 196   // ceil(50000/256)

// ---- scratch (device globals; no allocation allowed) ----
__device__ float g_S[NN * NR];
__device__ int   g_deg[NN];
__device__ int   g_off[NN + 1];
__device__ int   g_part[256];
__device__ int   g_cur[NN];
__device__ int2  g_cpack[NE];     // {src | (r<<16), bits(w)}
__device__ float g_emb0[NN * HD];
__device__ float g_emb1[NN * HD];
__device__ float g_emb2[NN * HD];
__device__ float g_T[(size_t)NR * NN * HD];  // TA_r tables only (64 MB, L2-resident)

// ---------------------------------------------------------------------------
__global__ void k_zero() {
  int stride = gridDim.x * blockDim.x;
  int t = blockIdx.x * blockDim.x + threadIdx.x;
  for (int i = t; i < NN * NR; i += stride) g_S[i] = 0.f;
  for (int i = t; i < NN; i += stride) g_deg[i] = 0;
}

__global__ void k_histwS(const float* __restrict__ etime, const int* __restrict__ eidx,
                         const int* __restrict__ etype, const float* __restrict__ plam,
                         const float* __restrict__ pbeta) {
  int e = blockIdx.x * blockDim.x + threadIdx.x;
  if (e >= NE) return;
  float w = plam[0] * expf(-pbeta[0] * fabsf(etime[e]));
  int d = eidx[NE + e];
  int r = etype[e];
  atomicAdd(&g_S[d * NR + r], w);
  atomicAdd(&g_deg[d], 1);
}

__global__ void k_scanA() {
  __shared__ int s[256];
  int tid = threadIdx.x;
  int i = blockIdx.x * 256 + tid;
  int v = (i < NN) ? g_deg[i] : 0;
  s[tid] = v;
  __syncthreads();
  #pragma unroll
  for (int d = 1; d < 256; d <<= 1) {
    int t = (tid >= d) ? s[tid - d] : 0;
    __syncthreads();
    s[tid] += t;
    __syncthreads();
  }
  if (i < NN) g_off[i] = s[tid] - v;
  if (tid == 255) g_part[blockIdx.x] = s[255];
}

__global__ void k_scanB() {
  __shared__ int s[256];
  int tid = threadIdx.x;
  int v = (tid < NCHUNK) ? g_part[tid] : 0;
  s[tid] = v;
  __syncthreads();
  #pragma unroll
  for (int d = 1; d < 256; d <<= 1) {
    int t = (tid >= d) ? s[tid - d] : 0;
    __syncthreads();
    s[tid] += t;
    __syncthreads();
  }
  if (tid < NCHUNK) g_part[tid] = s[tid] - v;
}

__global__ void k_scanC() {
  int i = blockIdx.x * 256 + threadIdx.x;
  if (i < NN) {
    int o = g_off[i] + g_part[i >> 8];
    g_off[i] = o;
    g_cur[i] = o;
  }
  if (i == 0) g_off[NN] = NE;
}

// Scatter edges into CSR order; recompute w (cheap) and pack into one int2.
__global__ void k_fill(const int* __restrict__ eidx, const int* __restrict__ etype,
                       const float* __restrict__ etime, const float* __restrict__ plam,
                       const float* __restrict__ pbeta) {
  int e = blockIdx.x * blockDim.x + threadIdx.x;
  if (e >= NE) return;
  int d = eidx[NE + e];
  float w = plam[0] * expf(-pbeta[0] * fabsf(etime[e]));
  int pos = atomicAdd(&g_cur[d], 1);
  g_cpack[pos] = make_int2(eidx[e] | (etype[e] << 16), __float_as_int(w));
}

// ---------------------------------------------------------------------------
// tf32 helpers (validated R3/R8: rel_err ~1e-6..2e-6)
__device__ __forceinline__ uint32_t f2tf(float f) {
  uint32_t r;
  asm("cvt.rna.tf32.f32 %0, %1;" : "=r"(r) : "f"(f));
  return r;
}
__device__ __forceinline__ void split_tf(float f, uint32_t& hi, uint32_t& lo) {
  hi = f2tf(f);
  lo = f2tf(f - __uint_as_float(hi));
}
__device__ __forceinline__ void mma_tf32(float c[4], uint32_t a0, uint32_t a1,
                                         uint32_t a2, uint32_t a3,
                                         uint32_t b0, uint32_t b1) {
  asm volatile(
      "mma.sync.aligned.m16n8k8.row.col.f32.tf32.tf32.f32 "
      "{%0,%1,%2,%3}, {%4,%5,%6,%7}, {%8,%9}, {%0,%1,%2,%3};"
      : "+f"(c[0]), "+f"(c[1]), "+f"(c[2]), "+f"(c[3])
      : "r"(a0), "r"(a1), "r"(a2), "r"(a3), "r"(b0), "r"(b1));
}

#define TRANS_SMEM (128 * SA_STRIDE * 4 + 8 * 8 * 32 * 16)  // 34816 + 32768 = 67584

// Fill 128x64 fp32 A tile into padded smem.
__device__ __forceinline__ void fill_sA(const float* __restrict__ Abase, int Kstride,
                                        int kofs, int row0, float* sA, int tid) {
  #pragma unroll 1
  for (int i = tid; i < 128 * 16; i += 256) {
    int r = i >> 4, c = i & 15;
    float4 v = make_float4(0.f, 0.f, 0.f, 0.f);
    if (row0 + r < NN)
      v = *(const float4*)(Abase + (size_t)(row0 + r) * Kstride + kofs + c * 4);
    *(float4*)(sA + r * SA_STRIDE + c * 4) = v;
  }
}

// Pre-split 64x64 W block into tf32 fragment order: sBf[ks][nc][lane] = (b0h,b1h,b0l,b1l).
__device__ __forceinline__ void fill_sBf(const float* __restrict__ W, uint4* sBf, int tid) {
  #pragma unroll 1
  for (int s = tid; s < 8 * 8 * 32; s += 256) {
    int ks = s >> 8;
    int nc = (s >> 5) & 7;
    int ln = s & 31;
    int lg = ln >> 2, ltg = ln & 3;
    int k1 = ks * 8 + ltg, k2 = k1 + 4;
    int n = nc * 8 + lg;
    uint32_t h1, l1, h2, l2;
    split_tf(__ldg(&W[k1 * HD + n]), h1, l1);
    split_tf(__ldg(&W[k2 * HD + n]), h2, l2);
    sBf[s] = make_uint4(h1, h2, l1, l2);
  }
}

// 3xTF32 accumulate of the (optionally row-scaled) smem A tile against sBf.
__device__ __forceinline__ void mma_rounds(const float* sA, const uint4* sBf,
                                           float acc[8][4], int lane, int warp,
                                           float sa, float sb) {
  int g = lane >> 2, tg = lane & 3;
  int wrow = warp * 16;
  #pragma unroll 1
  for (int ks = 0; ks < 8; ks++) {
    int kb = ks * 8;
    float af0 = sA[(wrow + g) * SA_STRIDE + kb + tg] * sa;
    float af1 = sA[(wrow + g + 8) * SA_STRIDE + kb + tg] * sb;
    float af2 = sA[(wrow + g) * SA_STRIDE + kb + tg + 4] * sa;
    float af3 = sA[(wrow + g + 8) * SA_STRIDE + kb + tg + 4] * sb;
    uint32_t ah0, al0, ah1, al1, ah2, al2, ah3, al3;
    split_tf(af0, ah0, al0);
    split_tf(af1, ah1, al1);
    split_tf(af2, ah2, al2);
    split_tf(af3, ah3, al3);
    const uint4* bp = sBf + ks * 8 * 32 + lane;
    #pragma unroll
    for (int nc = 0; nc < 8; nc++) {
      uint4 b = bp[nc * 32];
      mma_tf32(acc[nc], ah0, ah1, ah2, ah3, b.x, b.y);
      mma_tf32(acc[nc], ah0, ah1, ah2, ah3, b.z, b.w);
      mma_tf32(acc[nc], al0, al1, al2, al3, b.x, b.y);
    }
  }
}

// k_trans: TA_r = emb @ A_r (r = blockIdx.y, 5 tables only).
__global__ void __launch_bounds__(256) k_trans_mma(const float* __restrict__ relW, int layer) {
  extern __shared__ __align__(16) float smem[];
  float* sA = smem;
  uint4* sBf = (uint4*)(smem + 128 * SA_STRIDE);

  const float* emb = (layer == 0) ? g_emb0 : g_emb1;
  int r = blockIdx.y;
  const float* W = relW + (size_t)r * (2 * HD) * HD;  // A_r = first 64 rows

  int tid = threadIdx.x;
  int lane = tid & 31, warp = tid >> 5;
  int g = lane >> 2, tg = lane & 3;
  int row0 = blockIdx.x * 128;

  fill_sA(emb, HD, 0, row0, sA, tid);
  fill_sBf(W, sBf, tid);
  __syncthreads();

  float acc[8][4] = {};
  mma_rounds(sA, sBf, acc, lane, warp, 1.f, 1.f);

  float* out = g_T + (size_t)r * NN * HD;
  int ra = row0 + warp * 16 + g;
  int rb = ra + 8;
  #pragma unroll
  for (int nc = 0; nc < 8; nc++) {
    int col = nc * 8 + 2 * tg;
    if (ra < NN)
      *(float2*)(out + (size_t)ra * HD + col) = make_float2(acc[nc][0], acc[nc][1]);
    if (rb < NN)
      *(float2*)(out + (size_t)rb * HD + col) = make_float2(acc[nc][2], acc[nc][3]);
  }
}

// k_dst: emb_out[n] = sum_r S[n,r] * ((emb @ B_r)[n] + b_r)  -- row-scaled GEMM,
// A tile loaded once, 5 fragment rounds. k_edge_csr then adds the edge sum.
__global__ void __launch_bounds__(256) k_dst_mma(const float* __restrict__ relW,
                                                const float* __restrict__ relb, int layer) {
  extern __shared__ __align__(16) float smem[];
  float* sA = smem;
  uint4* sBf = (uint4*)(smem + 128 * SA_STRIDE);
  __shared__ float sBias[NR * HD];

  const float* emb = (layer == 0) ? g_emb0 : g_emb1;
  float* embo = (layer == 0) ? g_emb1 : g_emb2;

  int tid = threadIdx.x;
  int lane = tid & 31, warp = tid >> 5;
  int g = lane >> 2, tg = lane & 3;
  int row0 = blockIdx.x * 128;
  int ra = row0 + warp * 16 + g;
  int rb = ra + 8;

  fill_sA(emb, HD, 0, row0, sA, tid);
  for (int i = tid; i < NR * HD; i += 256) sBias[i] = __ldg(&relb[i]);

  float sa[NR], sb[NR];
  #pragma unroll
  for (int r = 0; r < NR; r++) {
    sa[r] = (ra < NN) ? __ldg(&g_S[ra * NR + r]) : 0.f;
    sb[r] = (rb < NN) ? __ldg(&g_S[rb * NR + r]) : 0.f;
  }

  float acc[8][4] = {};
  #pragma unroll 1
  for (int r = 0; r < NR; r++) {
    if (r) __syncthreads();  // WAR on sBf
    const float* W = relW + ((size_t)r * (2 * HD) + HD) * HD;  // B_r = second 64 rows
    fill_sBf(W, sBf, tid);
    __syncthreads();
    mma_rounds(sA, sBf, acc, lane, warp, sa[r], sb[r]);
  }

  #pragma unroll
  for (int nc = 0; nc < 8; nc++) {
    int col = nc * 8 + 2 * tg;
    float ba0 = 0.f, ba1 = 0.f, bb0 = 0.f, bb1 = 0.f;
    #pragma unroll
    for (int r = 0; r < NR; r++) {
      float b0 = sBias[r * HD + col], b1 = sBias[r * HD + col + 1];
      ba0 += sa[r] * b0; ba1 += sa[r] * b1;
      bb0 += sb[r] * b0; bb1 += sb[r] * b1;
    }
    if (ra < NN)
      *(float2*)(embo + (size_t)ra * HD + col) =
          make_float2(acc[nc][0] + ba0, acc[nc][1] + ba1);
    if (rb < NN)
      *(float2*)(embo + (size_t)rb * HD + col) =
          make_float2(acc[nc][2] + bb0, acc[nc][3] + bb1);
  }
}

// emb0 = x @ field_W + field_b (two k-halves).
__global__ void __launch_bounds__(256) k_emb0_mma(const float* __restrict__ x,
                                                 const float* __restrict__ fW,
                                                 const float* __restrict__ fb) {
  extern __shared__ __align__(16) float smem[];
  float* sA = smem;
  uint4* sBf = (uint4*)(smem + 128 * SA_STRIDE);

  int tid = threadIdx.x;
  int lane = tid & 31, warp = tid >> 5;
  int g = lane >> 2, tg = lane & 3;
  int row0 = blockIdx.x * 128;

  float acc[8][4] = {};
  #pragma unroll 1
  for (int h = 0; h < 2; h++) {
    if (h) __syncthreads();
    fill_sA(x, IND, h * 64, row0, sA, tid);
    fill_sBf(fW + (size_t)h * 64 * HD, sBf, tid);
    __syncthreads();
    mma_rounds(sA, sBf, acc, lane, warp, 1.f, 1.f);
  }

  int ra = row0 + warp * 16 + g;
  int rb = ra + 8;
  #pragma unroll
  for (int nc = 0; nc < 8; nc++) {
    int col = nc * 8 + 2 * tg;
    float b0 = __ldg(&fb[col]), b1 = __ldg(&fb[col + 1]);
    if (ra < NN)
      *(float2*)(g_emb0 + (size_t)ra * HD + col) =
          make_float2(acc[nc][0] + b0, acc[nc][1] + b1);
    if (rb < NN)
      *(float2*)(g_emb0 + (size_t)rb * HD + col) =
          make_float2(acc[nc][2] + b0, acc[nc][3] + b1);
  }
}

// out = sum_j leaky_relu(emb_j @ outW_j + outb_j), fused j-loop.
__global__ void __launch_bounds__(256) k_out_mma(
    const float* __restrict__ W0, const float* __restrict__ b0,
    const float* __restrict__ W1, const float* __restrict__ b1,
    const float* __restrict__ W2, const float* __restrict__ b2,
    float* __restrict__ out) {
  extern __shared__ __align__(16) float smem[];
  float* sA = smem;
  uint4* sBf = (uint4*)(smem + 128 * SA_STRIDE);

  int tid = threadIdx.x;
  int lane = tid & 31, warp = tid >> 5;
  int g = lane >> 2, tg = lane & 3;
  int row0 = blockIdx.x * 128;

  float o[8][4] = {};
  #pragma unroll 1
  for (int j = 0; j < 3; j++) {
    const float* emb = (j == 0) ? g_emb0 : (j == 1) ? g_emb1 : g_emb2;
    const float* W = (j == 0) ? W0 : (j == 1) ? W1 : W2;
    const float* b = (j == 0) ? b0 : (j == 1) ? b1 : b2;
    if (j) __syncthreads();
    fill_sA(emb, HD, 0, row0, sA, tid);
    fill_sBf(W, sBf, tid);
    __syncthreads();
    float acc[8][4] = {};
    mma_rounds(sA, sBf, acc, lane, warp, 1.f, 1.f);
    #pragma unroll
    for (int nc = 0; nc < 8; nc++) {
      int col = nc * 8 + 2 * tg;
      float bb0 = __ldg(&b[col]), bb1 = __ldg(&b[col + 1]);
      float z;
      z = acc[nc][0] + bb0; o[nc][0] += (z >= 0.f) ? z : NEG_SLOPE * z;
      z = acc[nc][1] + bb1; o[nc][1] += (z >= 0.f) ? z : NEG_SLOPE * z;
      z = acc[nc][2] + bb0; o[nc][2] += (z >= 0.f) ? z : NEG_SLOPE * z;
      z = acc[nc][3] + bb1; o[nc][3] += (z >= 0.f) ? z : NEG_SLOPE * z;
    }
  }

  int ra = row0 + warp * 16 + g;
  int rb = ra + 8;
  #pragma unroll
  for (int nc = 0; nc < 8; nc++) {
    int col = nc * 8 + 2 * tg;
    if (ra < NN)
      *(float2*)(out + (size_t)ra * HD + col) = make_float2(o[nc][0], o[nc][1]);
    if (rb < NN)
      *(float2*)(out + (size_t)rb * HD + col) = make_float2(o[nc][2], o[nc][3]);
  }
}

// ---------------------------------------------------------------------------
// CSR edge pass: emb_out[n] += sum_e w_e * TA[r_e][src_e]  (one warp per node).
__global__ void __launch_bounds__(256) k_edge_csr(int layer) {
  int node = (blockIdx.x * 256 + threadIdx.x) >> 5;
  if (node >= NN) return;
  int lane = threadIdx.x & 31;
  int grp = lane >> 4, fl = lane & 15;

  int beg = __ldg(&g_off[node]);
  int end = __ldg(&g_off[node + 1]);

  float4 a = make_float4(0.f, 0.f, 0.f, 0.f);
  #pragma unroll 4
  for (int j = beg + grp; j < end; j += 2) {
    int2 p = __ldg(&g_cpack[j]);
    int src = p.x & 0xFFFF;
    int r = p.x >> 16;
    float w = __int_as_float(p.y);
    float4 v = __ldg((const float4*)(g_T + ((size_t)r * NN + src) * HD) + fl);
    a.x += w * v.x; a.y += w * v.y; a.z += w * v.z; a.w += w * v.w;
  }
  a.x += __shfl_xor_sync(0xFFFFFFFF, a.x, 16);
  a.y += __shfl_xor_sync(0xFFFFFFFF, a.y, 16);
  a.z += __shfl_xor_sync(0xFFFFFFFF, a.z, 16);
  a.w += __shfl_xor_sync(0xFFFFFFFF, a.w, 16);

  if (grp == 0) {
    float* emb = (layer == 0) ? g_emb1 : g_emb2;
    float4 prev = *(float4*)(emb + (size_t)node * HD + fl * 4);  // dst term from k_dst_mma
    a.x += prev.x; a.y += prev.y; a.z += prev.z; a.w += prev.w;
    *(float4*)(emb + (size_t)node * HD + fl * 4) = a;
  }
}

// ---------------------------------------------------------------------------
extern "C" void kernel_launch(void* const* d_in, const int* in_sizes, int n_in,
                              void* d_out, int out_size) {
  const float* x     = (const float*)d_in[0];
  const int*   eidx  = (const int*)d_in[1];
  const int*   etype = (const int*)d_in[2];
  const float* etime = (const float*)d_in[3];
  const float* fW    = (const float*)d_in[4];
  const float* fb    = (const float*)d_in[5];
  const float* rW1   = (const float*)d_in[6];
  const float* rb1   = (const float*)d_in[7];
  const float* rW2   = (const float*)d_in[8];
  const float* rb2   = (const float*)d_in[9];
  const float* oW0   = (const float*)d_in[10];
  const float* ob0   = (const float*)d_in[11];
  const float* oW1   = (const float*)d_in[12];
  const float* ob1   = (const float*)d_in[13];
  const float* oW2   = (const float*)d_in[14];
  const float* ob2   = (const float*)d_in[15];
  const float* lam   = (const float*)d_in[16];
  const float* beta  = (const float*)d_in[17];
  float* out = (float*)d_out;

  const int TB = (NN + 127) / 128;        // 391
  dim3 gt(TB, NR);                        // 5 TA GEMMs only
  const int EB = (NE + 255) / 256;
  const int WB = (NN * 32 + 255) / 256;

  cudaFuncSetAttribute(k_trans_mma, cudaFuncAttributeMaxDynamicSharedMemorySize, TRANS_SMEM);
  cudaFuncSetAttribute(k_dst_mma, cudaFuncAttributeMaxDynamicSharedMemorySize, TRANS_SMEM);
  cudaFuncSetAttribute(k_emb0_mma, cudaFuncAttributeMaxDynamicSharedMemorySize, TRANS_SMEM);
  cudaFuncSetAttribute(k_out_mma, cudaFuncAttributeMaxDynamicSharedMemorySize, TRANS_SMEM);

  // CSR build (layer-independent)
  k_zero<<<1024, 256>>>();
  k_histwS<<<EB, 256>>>(etime, eidx, etype, lam, beta);
  k_scanA<<<NCHUNK, 256>>>();
  k_scanB<<<1, 256>>>();
  k_scanC<<<NCHUNK, 256>>>();
  k_fill<<<EB, 256>>>(eidx, etype, etime, lam, beta);

  k_emb0_mma<<<TB, 256, TRANS_SMEM>>>(x, fW, fb);

  // layer 1
  k_trans_mma<<<gt, 256, TRANS_SMEM>>>(rW1, 0);
  k_dst_mma<<<TB, 256, TRANS_SMEM>>>(rW1, rb1, 0);
  k_edge_csr<<<WB, 256>>>(0);

  // layer 2
  k_trans_mma<<<gt, 256, TRANS_SMEM>>>(rW2, 1);
  k_dst_mma<<<TB, 256, TRANS_SMEM>>>(rW2, rb2, 1);
  k_edge_csr<<<WB, 256>>>(1);

  k_out_mma<<<TB, 256, TRANS_SMEM>>>(oW0, ob0, oW1, ob1, oW2, ob2, out);
}

// round 11
// speedup vs baseline: 1.1091x; 1.1091x over previous
#include <cuda_runtime.h>
#include <cuda_fp16.h>
#include <cstdint>

#define NN 50000
#define NE 1600000
#define IND 128
#define HD 64
#define NR 5
#define SA_STRIDE 68
#define NEG_SLOPE 0.01f
#define NCHUNK 196   // ceil(50000/256)

// ---- scratch (device globals; no allocation allowed) ----
__device__ float g_w[NE];
__device__ float g_S[NN * NR];
__device__ int   g_deg[NN];
__device__ int   g_off[NN + 1];
__device__ int   g_part[256];
__device__ int   g_cur[NN];
__device__ int   g_cmeta[NE];     // src | (r<<16)
__device__ float g_cw[NE];
__device__ float g_emb0[NN * HD];
__device__ float g_emb1[NN * HD];
__device__ float g_emb2[NN * HD];
__device__ __half g_T[(size_t)10 * NN * HD];  // fp16 tables: TA_r (0..4), TB_r (5+r); 64 MB

// ---------------------------------------------------------------------------
__global__ void k_zero() {
  int stride = gridDim.x * blockDim.x;
  int t = blockIdx.x * blockDim.x + threadIdx.x;
  for (int i = t; i < NN * NR; i += stride) g_S[i] = 0.f;
  for (int i = t; i < NN; i += stride) g_deg[i] = 0;
}

__global__ void k_histwS(const float* __restrict__ etime, const int* __restrict__ eidx,
                         const int* __restrict__ etype, const float* __restrict__ plam,
                         const float* __restrict__ pbeta) {
  int e = blockIdx.x * blockDim.x + threadIdx.x;
  if (e >= NE) return;
  float w = plam[0] * expf(-pbeta[0] * fabsf(etime[e]));
  g_w[e] = w;
  int d = eidx[NE + e];
  int r = etype[e];
  atomicAdd(&g_S[d * NR + r], w);
  atomicAdd(&g_deg[d], 1);
}

__global__ void k_scanA() {
  __shared__ int s[256];
  int tid = threadIdx.x;
  int i = blockIdx.x * 256 + tid;
  int v = (i < NN) ? g_deg[i] : 0;
  s[tid] = v;
  __syncthreads();
  #pragma unroll
  for (int d = 1; d < 256; d <<= 1) {
    int t = (tid >= d) ? s[tid - d] : 0;
    __syncthreads();
    s[tid] += t;
    __syncthreads();
  }
  if (i < NN) g_off[i] = s[tid] - v;
  if (tid == 255) g_part[blockIdx.x] = s[255];
}

__global__ void k_scanB() {
  __shared__ int s[256];
  int tid = threadIdx.x;
  int v = (tid < NCHUNK) ? g_part[tid] : 0;
  s[tid] = v;
  __syncthreads();
  #pragma unroll
  for (int d = 1; d < 256; d <<= 1) {
    int t = (tid >= d) ? s[tid - d] : 0;
    __syncthreads();
    s[tid] += t;
    __syncthreads();
  }
  if (tid < NCHUNK) g_part[tid] = s[tid] - v;
}

__global__ void k_scanC() {
  int i = blockIdx.x * 256 + threadIdx.x;
  if (i < NN) {
    int o = g_off[i] + g_part[i >> 8];
    g_off[i] = o;
    g_cur[i] = o;
  }
  if (i == 0) g_off[NN] = NE;
}

__global__ void k_fill(const int* __restrict__ eidx, const int* __restrict__ etype) {
  int e = blockIdx.x * blockDim.x + threadIdx.x;
  if (e >= NE) return;
  int d = eidx[NE + e];
  int pos = atomicAdd(&g_cur[d], 1);
  g_cmeta[pos] = eidx[e] | (etype[e] << 16);
  g_cw[pos] = g_w[e];
}

// ---------------------------------------------------------------------------
// tf32 helpers (validated R3/R8: rel_err ~1e-6..2e-6)
__device__ __forceinline__ uint32_t f2tf(float f) {
  uint32_t r;
  asm("cvt.rna.tf32.f32 %0, %1;" : "=r"(r) : "f"(f));
  return r;
}
__device__ __forceinline__ void split_tf(float f, uint32_t& hi, uint32_t& lo) {
  hi = f2tf(f);
  lo = f2tf(f - __uint_as_float(hi));
}
__device__ __forceinline__ void mma_tf32(float c[4], uint32_t a0, uint32_t a1,
                                         uint32_t a2, uint32_t a3,
                                         uint32_t b0, uint32_t b1) {
  asm volatile(
      "mma.sync.aligned.m16n8k8.row.col.f32.tf32.tf32.f32 "
      "{%0,%1,%2,%3}, {%4,%5,%6,%7}, {%8,%9}, {%0,%1,%2,%3};"
      : "+f"(c[0]), "+f"(c[1]), "+f"(c[2]), "+f"(c[3])
      : "r"(a0), "r"(a1), "r"(a2), "r"(a3), "r"(b0), "r"(b1));
}

#define TRANS_SMEM (128 * SA_STRIDE * 4 + 8 * 8 * 32 * 16)  // 34816 + 32768 = 67584

// Shared tile routine (validated mapping from R8): fill 128x64 A tile + pre-split
// B fragments, accumulate 3xTF32 product into acc[8][4]. Caller owns pre-fill sync.
__device__ __forceinline__ void tile_fill_mma(
    const float* __restrict__ Abase, int Kstride, int kofs, int row0,
    const float* __restrict__ W,
    float* sA, uint4* sBf, float acc[8][4],
    int tid, int lane, int warp) {
  int g = lane >> 2, tg = lane & 3;
  #pragma unroll 1
  for (int i = tid; i < 128 * 16; i += 256) {
    int r = i >> 4, c = i & 15;
    float4 v = make_float4(0.f, 0.f, 0.f, 0.f);
    if (row0 + r < NN)
      v = *(const float4*)(Abase + (size_t)(row0 + r) * Kstride + kofs + c * 4);
    *(float4*)(sA + r * SA_STRIDE + c * 4) = v;
  }
  #pragma unroll 1
  for (int s = tid; s < 8 * 8 * 32; s += 256) {
    int ks = s >> 8;
    int nc = (s >> 5) & 7;
    int ln = s & 31;
    int lg = ln >> 2, ltg = ln & 3;
    int k1 = ks * 8 + ltg, k2 = k1 + 4;
    int n = nc * 8 + lg;
    uint32_t h1, l1, h2, l2;
    split_tf(__ldg(&W[k1 * HD + n]), h1, l1);
    split_tf(__ldg(&W[k2 * HD + n]), h2, l2);
    sBf[s] = make_uint4(h1, h2, l1, l2);
  }
  __syncthreads();

  int wrow = warp * 16;
  #pragma unroll 1
  for (int ks = 0; ks < 8; ks++) {
    int kb = ks * 8;
    float af0 = sA[(wrow + g) * SA_STRIDE + kb + tg];
    float af1 = sA[(wrow + g + 8) * SA_STRIDE + kb + tg];
    float af2 = sA[(wrow + g) * SA_STRIDE + kb + tg + 4];
    float af3 = sA[(wrow + g + 8) * SA_STRIDE + kb + tg + 4];
    uint32_t ah0, al0, ah1, al1, ah2, al2, ah3, al3;
    split_tf(af0, ah0, al0);
    split_tf(af1, ah1, al1);
    split_tf(af2, ah2, al2);
    split_tf(af3, ah3, al3);
    const uint4* bp = sBf + ks * 8 * 32 + lane;
    #pragma unroll
    for (int nc = 0; nc < 8; nc++) {
      uint4 b = bp[nc * 32];
      mma_tf32(acc[nc], ah0, ah1, ah2, ah3, b.x, b.y);
      mma_tf32(acc[nc], ah0, ah1, ah2, ah3, b.z, b.w);
      mma_tf32(acc[nc], al0, al1, al2, al3, b.x, b.y);
    }
  }
}

// k_trans: T[idx] = emb @ W_slice (idx = blockIdx.y), fp16 writeback.
__global__ void __launch_bounds__(256) k_trans_mma(const float* __restrict__ relW, int layer) {
  extern __shared__ __align__(16) float smem[];
  float* sA = smem;
  uint4* sBf = (uint4*)(smem + 128 * SA_STRIDE);

  const float* emb = (layer == 0) ? g_emb0 : g_emb1;
  int idx = blockIdx.y;
  int rr = idx % 5, half = idx / 5;
  const float* W = relW + ((size_t)rr * (2 * HD) + half * HD) * HD;

  int tid = threadIdx.x;
  int lane = tid & 31, warp = tid >> 5;
  int g = lane >> 2, tg = lane & 3;
  int row0 = blockIdx.x * 128;

  float acc[8][4] = {};
  tile_fill_mma(emb, HD, 0, row0, W, sA, sBf, acc, tid, lane, warp);

  __half* out = g_T + (size_t)idx * NN * HD;
  int ra = row0 + warp * 16 + g;
  int rb = ra + 8;
  #pragma unroll
  for (int nc = 0; nc < 8; nc++) {
    int col = nc * 8 + 2 * tg;
    if (ra < NN)
      *(__half2*)(out + (size_t)ra * HD + col) = __floats2half2_rn(acc[nc][0], acc[nc][1]);
    if (rb < NN)
      *(__half2*)(out + (size_t)rb * HD + col) = __floats2half2_rn(acc[nc][2], acc[nc][3]);
  }
}

// emb0 = x @ field_W + field_b, tensor cores, two k-halves.
__global__ void __launch_bounds__(256) k_emb0_mma(const float* __restrict__ x,
                                                 const float* __restrict__ fW,
                                                 const float* __restrict__ fb) {
  extern __shared__ __align__(16) float smem[];
  float* sA = smem;
  uint4* sBf = (uint4*)(smem + 128 * SA_STRIDE);

  int tid = threadIdx.x;
  int lane = tid & 31, warp = tid >> 5;
  int g = lane >> 2, tg = lane & 3;
  int row0 = blockIdx.x * 128;

  float acc[8][4] = {};
  tile_fill_mma(x, IND, 0, row0, fW, sA, sBf, acc, tid, lane, warp);
  __syncthreads();
  tile_fill_mma(x, IND, 64, row0, fW + (size_t)64 * HD, sA, sBf, acc, tid, lane, warp);

  int ra = row0 + warp * 16 + g;
  int rb = ra + 8;
  #pragma unroll
  for (int nc = 0; nc < 8; nc++) {
    int col = nc * 8 + 2 * tg;
    float b0 = __ldg(&fb[col]), b1 = __ldg(&fb[col + 1]);
    if (ra < NN)
      *(float2*)(g_emb0 + (size_t)ra * HD + col) =
          make_float2(acc[nc][0] + b0, acc[nc][1] + b1);
    if (rb < NN)
      *(float2*)(g_emb0 + (size_t)rb * HD + col) =
          make_float2(acc[nc][2] + b0, acc[nc][3] + b1);
  }
}

// out = sum_j leaky_relu(emb_j @ outW_j + outb_j), fused j-loop.
__global__ void __launch_bounds__(256) k_out_mma(
    const float* __restrict__ W0, const float* __restrict__ b0,
    const float* __restrict__ W1, const float* __restrict__ b1,
    const float* __restrict__ W2, const float* __restrict__ b2,
    float* __restrict__ out) {
  extern __shared__ __align__(16) float smem[];
  float* sA = smem;
  uint4* sBf = (uint4*)(smem + 128 * SA_STRIDE);

  int tid = threadIdx.x;
  int lane = tid & 31, warp = tid >> 5;
  int g = lane >> 2, tg = lane & 3;
  int row0 = blockIdx.x * 128;

  float o[8][4] = {};
  #pragma unroll 1
  for (int j = 0; j < 3; j++) {
    const float* emb = (j == 0) ? g_emb0 : (j == 1) ? g_emb1 : g_emb2;
    const float* W = (j == 0) ? W0 : (j == 1) ? W1 : W2;
    const float* b = (j == 0) ? b0 : (j == 1) ? b1 : b2;
    if (j) __syncthreads();
    float acc[8][4] = {};
    tile_fill_mma(emb, HD, 0, row0, W, sA, sBf, acc, tid, lane, warp);
    #pragma unroll
    for (int nc = 0; nc < 8; nc++) {
      int col = nc * 8 + 2 * tg;
      float bb0 = __ldg(&b[col]), bb1 = __ldg(&b[col + 1]);
      float z;
      z = acc[nc][0] + bb0; o[nc][0] += (z >= 0.f) ? z : NEG_SLOPE * z;
      z = acc[nc][1] + bb1; o[nc][1] += (z >= 0.f) ? z : NEG_SLOPE * z;
      z = acc[nc][2] + bb0; o[nc][2] += (z >= 0.f) ? z : NEG_SLOPE * z;
      z = acc[nc][3] + bb1; o[nc][3] += (z >= 0.f) ? z : NEG_SLOPE * z;
    }
  }

  int ra = row0 + warp * 16 + g;
  int rb = ra + 8;
  #pragma unroll
  for (int nc = 0; nc < 8; nc++) {
    int col = nc * 8 + 2 * tg;
    if (ra < NN)
      *(float2*)(out + (size_t)ra * HD + col) = make_float2(o[nc][0], o[nc][1]);
    if (rb < NN)
      *(float2*)(out + (size_t)rb * HD + col) = make_float2(o[nc][2], o[nc][3]);
  }
}

// ---------------------------------------------------------------------------
// CSR edge pass fused with dst-term (one warp per node, no atomics, fp16 gathers).
__global__ void __launch_bounds__(256) k_edge_csr(const float* __restrict__ relb, int layer) {
  int node = (blockIdx.x * 256 + threadIdx.x) >> 5;
  if (node >= NN) return;
  int lane = threadIdx.x & 31;
  int grp = lane >> 4, fl = lane & 15;

  int beg = __ldg(&g_off[node]);
  int end = __ldg(&g_off[node + 1]);

  float4 a = make_float4(0.f, 0.f, 0.f, 0.f);
  #pragma unroll 4
  for (int j = beg + grp; j < end; j += 2) {
    int m = __ldg(&g_cmeta[j]);
    float w = __ldg(&g_cw[j]);
    int src = m & 0xFFFF;
    int r = m >> 16;
    // lane fl covers halves [fl*4, fl*4+4) of the 64-half row = one uint2 (8 B)
    const uint2* rowp = (const uint2*)(g_T + ((size_t)r * NN + src) * HD);
    uint2 raw = __ldg(rowp + fl);
    float2 f0 = __half22float2(*(__half2*)&raw.x);
    float2 f1 = __half22float2(*(__half2*)&raw.y);
    a.x += w * f0.x; a.y += w * f0.y; a.z += w * f1.x; a.w += w * f1.y;
  }
  a.x += __shfl_xor_sync(0xFFFFFFFF, a.x, 16);
  a.y += __shfl_xor_sync(0xFFFFFFFF, a.y, 16);
  a.z += __shfl_xor_sync(0xFFFFFFFF, a.z, 16);
  a.w += __shfl_xor_sync(0xFFFFFFFF, a.w, 16);

  if (grp == 0) {
    #pragma unroll
    for (int r = 0; r < NR; r++) {
      float s = __ldg(&g_S[node * NR + r]);
      const uint2* tp = (const uint2*)(g_T + ((size_t)(5 + r) * NN + node) * HD);
      uint2 raw = __ldg(tp + fl);
      float2 t0 = __half22float2(*(__half2*)&raw.x);
      float2 t1 = __half22float2(*(__half2*)&raw.y);
      float4 b4 = __ldg((const float4*)(relb + r * HD) + fl);
      a.x += s * (t0.x + b4.x);
      a.y += s * (t0.y + b4.y);
      a.z += s * (t1.x + b4.z);
      a.w += s * (t1.y + b4.w);
    }
    float* emb = (layer == 0) ? g_emb1 : g_emb2;
    *(float4*)(emb + (size_t)node * HD + fl * 4) = a;
  }
}

// ---------------------------------------------------------------------------
extern "C" void kernel_launch(void* const* d_in, const int* in_sizes, int n_in,
                              void* d_out, int out_size) {
  const float* x     = (const float*)d_in[0];
  const int*   eidx  = (const int*)d_in[1];
  const int*   etype = (const int*)d_in[2];
  const float* etime = (const float*)d_in[3];
  const float* fW    = (const float*)d_in[4];
  const float* fb    = (const float*)d_in[5];
  const float* rW1   = (const float*)d_in[6];
  const float* rb1   = (const float*)d_in[7];
  const float* rW2   = (const float*)d_in[8];
  const float* rb2   = (const float*)d_in[9];
  const float* oW0   = (const float*)d_in[10];
  const float* ob0   = (const float*)d_in[11];
  const float* oW1   = (const float*)d_in[12];
  const float* ob1   = (const float*)d_in[13];
  const float* oW2   = (const float*)d_in[14];
  const float* ob2   = (const float*)d_in[15];
  const float* lam   = (const float*)d_in[16];
  const float* beta  = (const float*)d_in[17];
  float* out = (float*)d_out;

  const int TB = (NN + 127) / 128;        // 391 (tensor tiles)
  dim3 gt(TB, 10);
  const int EB = (NE + 255) / 256;        // 6250
  const int WB = (NN * 32 + 255) / 256;   // one warp per node

  cudaFuncSetAttribute(k_trans_mma, cudaFuncAttributeMaxDynamicSharedMemorySize, TRANS_SMEM);
  cudaFuncSetAttribute(k_emb0_mma, cudaFuncAttributeMaxDynamicSharedMemorySize, TRANS_SMEM);
  cudaFuncSetAttribute(k_out_mma, cudaFuncAttributeMaxDynamicSharedMemorySize, TRANS_SMEM);

  // CSR build (layer-independent)
  k_zero<<<1024, 256>>>();
  k_histwS<<<EB, 256>>>(etime, eidx, etype, lam, beta);
  k_scanA<<<NCHUNK, 256>>>();
  k_scanB<<<1, 256>>>();
  k_scanC<<<NCHUNK, 256>>>();
  k_fill<<<EB, 256>>>(eidx, etype);

  k_emb0_mma<<<TB, 256, TRANS_SMEM>>>(x, fW, fb);

  // layer 1
  k_trans_mma<<<gt, 256, TRANS_SMEM>>>(rW1, 0);
  k_edge_csr<<<WB, 256>>>(rb1, 0);

  // layer 2
  k_trans_mma<<<gt, 256, TRANS_SMEM>>>(rW2, 1);
  k_edge_csr<<<WB, 256>>>(rb2, 1);

  k_out_mma<<<TB, 256, TRANS_SMEM>>>(oW0, ob0, oW1, ob1, oW2, ob2, out);
}

// round 12
// speedup vs baseline: 1.1393x; 1.0272x over previous
#include <cuda_runtime.h>
#include <cuda_fp16.h>
#include <cstdint>

#define NN 50000
#define NE 1600000
#define IND 128
#define HD 64
#define NR 5
#define SA_STRIDE 68
#define NEG_SLOPE 0.01f
#define NCHUNK 196   // ceil(50000/256)
#define TBX 391      // ceil(50000/128) tensor row tiles
#define HB 1563      // ceil(NE/1024) hist/fill blocks (4 edges/thread)

// ---- scratch (device globals; no allocation allowed) ----
__device__ float g_S[NN * NR];
__device__ int   g_deg[NN];
__device__ int   g_off[NN + 1];
__device__ int   g_part[256];
__device__ int   g_cur[NN];
__device__ int2  g_cpack[NE];     // {src | (r<<16), bits(w)}
__device__ float g_emb0[NN * HD];
__device__ float g_emb1[NN * HD];
__device__ float g_emb2[NN * HD];
__device__ __half g_T[(size_t)10 * NN * HD];  // fp16: TA_r (0..4), TB_r (5+r); 64 MB

// ---------------------------------------------------------------------------
// tf32 helpers (validated R3/R8)
__device__ __forceinline__ uint32_t f2tf(float f) {
  uint32_t r;
  asm("cvt.rna.tf32.f32 %0, %1;" : "=r"(r) : "f"(f));
  return r;
}
__device__ __forceinline__ void split_tf(float f, uint32_t& hi, uint32_t& lo) {
  hi = f2tf(f);
  lo = f2tf(f - __uint_as_float(hi));
}
__device__ __forceinline__ void mma_tf32(float c[4], uint32_t a0, uint32_t a1,
                                         uint32_t a2, uint32_t a3,
                                         uint32_t b0, uint32_t b1) {
  asm volatile(
      "mma.sync.aligned.m16n8k8.row.col.f32.tf32.tf32.f32 "
      "{%0,%1,%2,%3}, {%4,%5,%6,%7}, {%8,%9}, {%0,%1,%2,%3};"
      : "+f"(c[0]), "+f"(c[1]), "+f"(c[2]), "+f"(c[3])
      : "r"(a0), "r"(a1), "r"(a2), "r"(a3), "r"(b0), "r"(b1));
}

#define TRANS_SMEM (128 * SA_STRIDE * 4 + 8 * 8 * 32 * 16)  // 67584

// Shared tile routine (validated R8/R11).
__device__ __forceinline__ void tile_fill_mma(
    const float* __restrict__ Abase, int Kstride, int kofs, int row0,
    const float* __restrict__ W,
    float* sA, uint4* sBf, float acc[8][4],
    int tid, int lane, int warp) {
  int g = lane >> 2, tg = lane & 3;
  #pragma unroll 1
  for (int i = tid; i < 128 * 16; i += 256) {
    int r = i >> 4, c = i & 15;
    float4 v = make_float4(0.f, 0.f, 0.f, 0.f);
    if (row0 + r < NN)
      v = *(const float4*)(Abase + (size_t)(row0 + r) * Kstride + kofs + c * 4);
    *(float4*)(sA + r * SA_STRIDE + c * 4) = v;
  }
  #pragma unroll 1
  for (int s = tid; s < 8 * 8 * 32; s += 256) {
    int ks = s >> 8;
    int nc = (s >> 5) & 7;
    int ln = s & 31;
    int lg = ln >> 2, ltg = ln & 3;
    int k1 = ks * 8 + ltg, k2 = k1 + 4;
    int n = nc * 8 + lg;
    uint32_t h1, l1, h2, l2;
    split_tf(__ldg(&W[k1 * HD + n]), h1, l1);
    split_tf(__ldg(&W[k2 * HD + n]), h2, l2);
    sBf[s] = make_uint4(h1, h2, l1, l2);
  }
  __syncthreads();

  int wrow = warp * 16;
  #pragma unroll 1
  for (int ks = 0; ks < 8; ks++) {
    int kb = ks * 8;
    float af0 = sA[(wrow + g) * SA_STRIDE + kb + tg];
    float af1 = sA[(wrow + g + 8) * SA_STRIDE + kb + tg];
    float af2 = sA[(wrow + g) * SA_STRIDE + kb + tg + 4];
    float af3 = sA[(wrow + g + 8) * SA_STRIDE + kb + tg + 4];
    uint32_t ah0, al0, ah1, al1, ah2, al2, ah3, al3;
    split_tf(af0, ah0, al0);
    split_tf(af1, ah1, al1);
    split_tf(af2, ah2, al2);
    split_tf(af3, ah3, al3);
    const uint4* bp = sBf + ks * 8 * 32 + lane;
    #pragma unroll
    for (int nc = 0; nc < 8; nc++) {
      uint4 b = bp[nc * 32];
      mma_tf32(acc[nc], ah0, ah1, ah2, ah3, b.x, b.y);
      mma_tf32(acc[nc], ah0, ah1, ah2, ah3, b.z, b.w);
      mma_tf32(acc[nc], al0, al1, al2, al3, b.x, b.y);
    }
  }
}

// trans body: T[idx] = emb @ W_slice, fp16 writeback (validated R11).
__device__ __forceinline__ void trans_body(const float* __restrict__ relW,
                                           const float* __restrict__ emb,
                                           int idx, int bx, char* smraw) {
  float* sA = (float*)smraw;
  uint4* sBf = (uint4*)(smraw + 128 * SA_STRIDE * 4);
  int rr = idx % 5, half = idx / 5;
  const float* W = relW + ((size_t)rr * (2 * HD) + half * HD) * HD;

  int tid = threadIdx.x;
  int lane = tid & 31, warp = tid >> 5;
  int g = lane >> 2, tg = lane & 3;
  int row0 = bx * 128;

  float acc[8][4] = {};
  tile_fill_mma(emb, HD, 0, row0, W, sA, sBf, acc, tid, lane, warp);

  __half* out = g_T + (size_t)idx * NN * HD;
  int ra = row0 + warp * 16 + g;
  int rb = ra + 8;
  #pragma unroll
  for (int nc = 0; nc < 8; nc++) {
    int col = nc * 8 + 2 * tg;
    if (ra < NN)
      *(__half2*)(out + (size_t)ra * HD + col) = __floats2half2_rn(acc[nc][0], acc[nc][1]);
    if (rb < NN)
      *(__half2*)(out + (size_t)rb * HD + col) = __floats2half2_rn(acc[nc][2], acc[nc][3]);
  }
}

// ---------------------------------------------------------------------------
// K_pre: blocks [0,HB) -> edge histogram (4 edges/thread); [HB, HB+TBX) -> emb0.
__global__ void __launch_bounds__(256) k_pre(
    const float* __restrict__ etime, const int* __restrict__ eidx,
    const int* __restrict__ etype, const float* __restrict__ plam,
    const float* __restrict__ pbeta,
    const float* __restrict__ x, const float* __restrict__ fW,
    const float* __restrict__ fb) {
  extern __shared__ __align__(16) char smraw[];
  if (blockIdx.x < HB) {
    float lam = plam[0], beta = pbeta[0];
    int e0 = blockIdx.x * 1024 + threadIdx.x;
    #pragma unroll
    for (int k = 0; k < 4; k++) {
      int e = e0 + k * 256;
      if (e < NE) {
        float w = lam * expf(-beta * fabsf(__ldg(&etime[e])));
        int d = __ldg(&eidx[NE + e]);
        int r = __ldg(&etype[e]);
        atomicAdd(&g_S[d * NR + r], w);
        atomicAdd(&g_deg[d], 1);
      }
    }
    return;
  }
  // emb0 = x @ field_W + field_b (two k-halves)
  float* sA = (float*)smraw;
  uint4* sBf = (uint4*)(smraw + 128 * SA_STRIDE * 4);
  int tid = threadIdx.x;
  int lane = tid & 31, warp = tid >> 5;
  int g = lane >> 2, tg = lane & 3;
  int row0 = (blockIdx.x - HB) * 128;

  float acc[8][4] = {};
  tile_fill_mma(x, IND, 0, row0, fW, sA, sBf, acc, tid, lane, warp);
  __syncthreads();
  tile_fill_mma(x, IND, 64, row0, fW + (size_t)64 * HD, sA, sBf, acc, tid, lane, warp);

  int ra = row0 + warp * 16 + g;
  int rb = ra + 8;
  #pragma unroll
  for (int nc = 0; nc < 8; nc++) {
    int col = nc * 8 + 2 * tg;
    float b0 = __ldg(&fb[col]), b1 = __ldg(&fb[col + 1]);
    if (ra < NN)
      *(float2*)(g_emb0 + (size_t)ra * HD + col) =
          make_float2(acc[nc][0] + b0, acc[nc][1] + b1);
    if (rb < NN)
      *(float2*)(g_emb0 + (size_t)rb * HD + col) =
          make_float2(acc[nc][2] + b0, acc[nc][3] + b1);
  }
}

// ---------------------------------------------------------------------------
__global__ void k_scanA() {
  __shared__ int s[256];
  int tid = threadIdx.x;
  int i = blockIdx.x * 256 + tid;
  int v = (i < NN) ? g_deg[i] : 0;
  s[tid] = v;
  __syncthreads();
  #pragma unroll
  for (int d = 1; d < 256; d <<= 1) {
    int t = (tid >= d) ? s[tid - d] : 0;
    __syncthreads();
    s[tid] += t;
    __syncthreads();
  }
  if (i < NN) g_off[i] = s[tid] - v;
  if (tid == 255) g_part[blockIdx.x] = s[255];
}

__global__ void k_scanB() {
  __shared__ int s[256];
  int tid = threadIdx.x;
  int v = (tid < NCHUNK) ? g_part[tid] : 0;
  s[tid] = v;
  __syncthreads();
  #pragma unroll
  for (int d = 1; d < 256; d <<= 1) {
    int t = (tid >= d) ? s[tid - d] : 0;
    __syncthreads();
    s[tid] += t;
    __syncthreads();
  }
  if (tid < NCHUNK) g_part[tid] = s[tid] - v;
}

__global__ void k_scanC() {
  int i = blockIdx.x * 256 + threadIdx.x;
  if (i < NN) {
    int o = g_off[i] + g_part[i >> 8];
    g_off[i] = o;
    g_cur[i] = o;
  }
  if (i == 0) g_off[NN] = NE;
}

// ---------------------------------------------------------------------------
// K_mid: blocks [0,HB) -> CSR fill (4 edges/thread, int2 pack, recompute w);
//        blocks [HB, HB+10*TBX) -> trans layer-1 GEMMs.
__global__ void __launch_bounds__(256) k_mid(
    const int* __restrict__ eidx, const int* __restrict__ etype,
    const float* __restrict__ etime, const float* __restrict__ plam,
    const float* __restrict__ pbeta,
    const float* __restrict__ relW) {
  extern __shared__ __align__(16) char smraw[];
  if (blockIdx.x < HB) {
    float lam = plam[0], beta = pbeta[0];
    int e0 = blockIdx.x * 1024 + threadIdx.x;
    #pragma unroll
    for (int k = 0; k < 4; k++) {
      int e = e0 + k * 256;
      if (e < NE) {
        int d = __ldg(&eidx[NE + e]);
        float w = lam * expf(-beta * fabsf(__ldg(&etime[e])));
        int pos = atomicAdd(&g_cur[d], 1);
        g_cpack[pos] = make_int2(__ldg(&eidx[e]) | (__ldg(&etype[e]) << 16),
                                 __float_as_int(w));
      }
    }
    return;
  }
  int t = blockIdx.x - HB;
  trans_body(relW, g_emb0, t / TBX, t % TBX, smraw);
}

// Layer-2 trans (no merge partner).
__global__ void __launch_bounds__(256) k_trans2(const float* __restrict__ relW) {
  extern __shared__ __align__(16) char smraw[];
  trans_body(relW, g_emb1, blockIdx.y, blockIdx.x, smraw);
}

// ---------------------------------------------------------------------------
// CSR edge pass fused with dst-term (one warp/node, fp16 gathers, int2 meta).
__global__ void __launch_bounds__(256) k_edge_csr(const float* __restrict__ relb, int layer) {
  int node = (blockIdx.x * 256 + threadIdx.x) >> 5;
  if (node >= NN) return;
  int lane = threadIdx.x & 31;
  int grp = lane >> 4, fl = lane & 15;

  int beg = __ldg(&g_off[node]);
  int end = __ldg(&g_off[node + 1]);

  float4 a = make_float4(0.f, 0.f, 0.f, 0.f);
  #pragma unroll 4
  for (int j = beg + grp; j < end; j += 2) {
    int2 p = __ldg(&g_cpack[j]);
    int src = p.x & 0xFFFF;
    int r = p.x >> 16;
    float w = __int_as_float(p.y);
    const uint2* rowp = (const uint2*)(g_T + ((size_t)r * NN + src) * HD);
    uint2 raw = __ldg(rowp + fl);
    float2 f0 = __half22float2(*(__half2*)&raw.x);
    float2 f1 = __half22float2(*(__half2*)&raw.y);
    a.x += w * f0.x; a.y += w * f0.y; a.z += w * f1.x; a.w += w * f1.y;
  }
  a.x += __shfl_xor_sync(0xFFFFFFFF, a.x, 16);
  a.y += __shfl_xor_sync(0xFFFFFFFF, a.y, 16);
  a.z += __shfl_xor_sync(0xFFFFFFFF, a.z, 16);
  a.w += __shfl_xor_sync(0xFFFFFFFF, a.w, 16);

  if (grp == 0) {
    #pragma unroll
    for (int r = 0; r < NR; r++) {
      float s = __ldg(&g_S[node * NR + r]);
      const uint2* tp = (const uint2*)(g_T + ((size_t)(5 + r) * NN + node) * HD);
      uint2 raw = __ldg(tp + fl);
      float2 t0 = __half22float2(*(__half2*)&raw.x);
      float2 t1 = __half22float2(*(__half2*)&raw.y);
      float4 b4 = __ldg((const float4*)(relb + r * HD) + fl);
      a.x += s * (t0.x + b4.x);
      a.y += s * (t0.y + b4.y);
      a.z += s * (t1.x + b4.z);
      a.w += s * (t1.y + b4.w);
    }
    float* emb = (layer == 0) ? g_emb1 : g_emb2;
    *(float4*)(emb + (size_t)node * HD + fl * 4) = a;
  }
}

// out = sum_j leaky_relu(emb_j @ outW_j + outb_j), fused j-loop.
__global__ void __launch_bounds__(256) k_out_mma(
    const float* __restrict__ W0, const float* __restrict__ b0,
    const float* __restrict__ W1, const float* __restrict__ b1,
    const float* __restrict__ W2, const float* __restrict__ b2,
    float* __restrict__ out) {
  extern __shared__ __align__(16) char smraw[];
  float* sA = (float*)smraw;
  uint4* sBf = (uint4*)(smraw + 128 * SA_STRIDE * 4);

  int tid = threadIdx.x;
  int lane = tid & 31, warp = tid >> 5;
  int g = lane >> 2, tg = lane & 3;
  int row0 = blockIdx.x * 128;

  float o[8][4] = {};
  #pragma unroll 1
  for (int j = 0; j < 3; j++) {
    const float* emb = (j == 0) ? g_emb0 : (j == 1) ? g_emb1 : g_emb2;
    const float* W = (j == 0) ? W0 : (j == 1) ? W1 : W2;
    const float* b = (j == 0) ? b0 : (j == 1) ? b1 : b2;
    if (j) __syncthreads();
    float acc[8][4] = {};
    tile_fill_mma(emb, HD, 0, row0, W, sA, sBf, acc, tid, lane, warp);
    #pragma unroll
    for (int nc = 0; nc < 8; nc++) {
      int col = nc * 8 + 2 * tg;
      float bb0 = __ldg(&b[col]), bb1 = __ldg(&b[col + 1]);
      float z;
      z = acc[nc][0] + bb0; o[nc][0] += (z >= 0.f) ? z : NEG_SLOPE * z;
      z = acc[nc][1] + bb1; o[nc][1] += (z >= 0.f) ? z : NEG_SLOPE * z;
      z = acc[nc][2] + bb0; o[nc][2] += (z >= 0.f) ? z : NEG_SLOPE * z;
      z = acc[nc][3] + bb1; o[nc][3] += (z >= 0.f) ? z : NEG_SLOPE * z;
    }
  }

  int ra = row0 + warp * 16 + g;
  int rb = ra + 8;
  #pragma unroll
  for (int nc = 0; nc < 8; nc++) {
    int col = nc * 8 + 2 * tg;
    if (ra < NN)
      *(float2*)(out + (size_t)ra * HD + col) = make_float2(o[nc][0], o[nc][1]);
    if (rb < NN)
      *(float2*)(out + (size_t)rb * HD + col) = make_float2(o[nc][2], o[nc][3]);
  }
}

// ---------------------------------------------------------------------------
extern "C" void kernel_launch(void* const* d_in, const int* in_sizes, int n_in,
                              void* d_out, int out_size) {
  const float* x     = (const float*)d_in[0];
  const int*   eidx  = (const int*)d_in[1];
  const int*   etype = (const int*)d_in[2];
  const float* etime = (const float*)d_in[3];
  const float* fW    = (const float*)d_in[4];
  const float* fb    = (const float*)d_in[5];
  const float* rW1   = (const float*)d_in[6];
  const float* rb1   = (const float*)d_in[7];
  const float* rW2   = (const float*)d_in[8];
  const float* rb2   = (const float*)d_in[9];
  const float* oW0   = (const float*)d_in[10];
  const float* ob0   = (const float*)d_in[11];
  const float* oW1   = (const float*)d_in[12];
  const float* ob1   = (const float*)d_in[13];
  const float* oW2   = (const float*)d_in[14];
  const float* ob2   = (const float*)d_in[15];
  const float* lam   = (const float*)d_in[16];
  const float* beta  = (const float*)d_in[17];
  float* out = (float*)d_out;

  const int WB = (NN * 32 + 255) / 256;   // one warp per node
  dim3 gt2(TBX, 10);

  cudaFuncSetAttribute(k_pre, cudaFuncAttributeMaxDynamicSharedMemorySize, TRANS_SMEM);
  cudaFuncSetAttribute(k_mid, cudaFuncAttributeMaxDynamicSharedMemorySize, TRANS_SMEM);
  cudaFuncSetAttribute(k_trans2, cudaFuncAttributeMaxDynamicSharedMemorySize, TRANS_SMEM);
  cudaFuncSetAttribute(k_out_mma, cudaFuncAttributeMaxDynamicSharedMemorySize, TRANS_SMEM);

  // Zero S/deg via graph-capturable memset nodes.
  void *pS = nullptr, *pDeg = nullptr;
  cudaGetSymbolAddress(&pS, g_S);
  cudaGetSymbolAddress(&pDeg, g_deg);
  cudaMemsetAsync(pS, 0, NN * NR * sizeof(float));
  cudaMemsetAsync(pDeg, 0, NN * sizeof(int));

  // histwS || emb0
  k_pre<<<HB + TBX, 256, TRANS_SMEM>>>(etime, eidx, etype, lam, beta, x, fW, fb);
  k_scanA<<<NCHUNK, 256>>>();
  k_scanB<<<1, 256>>>();
  k_scanC<<<NCHUNK, 256>>>();

  // fill || trans layer-1
  k_mid<<<HB + 10 * TBX, 256, TRANS_SMEM>>>(eidx, etype, etime, lam, beta, rW1);
  k_edge_csr<<<WB, 256>>>(rb1, 0);

  // layer 2
  k_trans2<<<gt2, 256, TRANS_SMEM>>>(rW2);
  k_edge_csr<<<WB, 256>>>(rb2, 1);

  k_out_mma<<<TBX, 256, TRANS_SMEM>>>(oW0, ob0, oW1, ob1, oW2, ob2, out);
}